// round 16
// baseline (speedup 1.0000x reference)
#include <cuda_runtime.h>
#include <cuda_fp16.h>
#include <cstdint>
#include <cstring>

// ============================================================================
// FlattenedObsEncoder: out[16384,1024] = (gather(W_embed,x)+b_embed) @ W_dense + b_dense
// fp16 m16n8k16 mma.sync GEMM, fp32 accumulation.
// R16 = R14 structure (fixed n-band per CTA -> B stays L2/L1-warm; R11 inner
// loop untouched; epilogue overlapped with next-tile prefetch) with:
//   - GRID 296 (= 8 bands x 37, fully resident, no overflow wave)
//   - per-band atomic m-tile scheduler (8 counters, jitter-absorbing)
// CTA tile 128x128, 256 threads, warp tile 32x64, 2 CTAs/SM, 3-stage pipeline.
// ============================================================================

#define B_SZ   16384
#define P_SZ   256
#define K_SZ   1024
#define NCLS   1024
#define N_SZ   1024
#define MT     128
#define NT     128
#define NKS    (K_SZ / 16)    // 64 global k16-steps
#define KSC    4              // ksteps per chunk
#define NCHUNK (NKS / KSC)    // 16
#define THREADS 256
#define A_U4   1024
#define B_U4   1024
#define STAGE_U4 (A_U4 + B_U4)               // 2048 uint4 = 32 KB
#define NSTAGE 3
#define SMEM_BYTES (STAGE_U4 * NSTAGE * 16)  // 98,304 B -> 2 CTAs/SM
#define GRID_P 296                            // 8 bands x 37 CTAs, all resident
#define M_TILES (B_SZ / MT)                   // 128 m-tiles per band

__device__ uint4 g_Bpack[(size_t)(N_SZ / 16) * NKS * 32];
__device__ uint4 g_Apack[(size_t)(B_SZ / 16) * NKS * 32];
__device__ int   g_mctr[8];                   // per-band m counters (reset in prepass)

// ---------------------------------------------------------------------------
__device__ __forceinline__ uint32_t smem_u32(const void* p) {
    uint32_t a;
    asm("{ .reg .u64 t; cvta.to.shared.u64 t, %1; cvt.u32.u64 %0, t; }" : "=r"(a) : "l"(p));
    return a;
}
__device__ __forceinline__ void cp16(uint32_t s, const void* g) {
    asm volatile("cp.async.cg.shared.global [%0], [%1], 16;" :: "r"(s), "l"(g));
}
#define CP_COMMIT() asm volatile("cp.async.commit_group;" ::: "memory")
#define CP_WAIT1()  asm volatile("cp.async.wait_group 1;" ::: "memory")

__device__ __forceinline__ uint32_t h2pack(float lo, float hi) {
    const __half2 h = __floats2half2_rn(lo, hi);   // low half = lo
    uint32_t u;
    memcpy(&u, &h, 4);
    return u;
}

// ---------------------------------------------------------------------------
// Merged prepass.  Blocks [0,512): W_dense -> B-fragment pack.
//                  Blocks [512,640): gather+bias -> A-fragment pack (128 rows).
// Also resets the per-band m counters.
// ---------------------------------------------------------------------------
#define XS 260   // padded x-row stride in ints

__global__ void __launch_bounds__(256)
pack_all_kernel(const float* __restrict__ Wd,
                const int* __restrict__ x, const float* __restrict__ We,
                const float* __restrict__ be) {
    __shared__ uint32_t sH[NCLS * 2];
    __shared__ int sX[16 * XS];

    const int tid = threadIdx.x;
    const int lane = tid & 31;
    const int g = lane >> 2, t4 = lane & 3;

    if (blockIdx.x == 0 && tid < 8) g_mctr[tid] = 0;

    if (blockIdx.x < 512) {
        // ---- B pack: block = (nb16, ks-group of 8) ----
        const int nb16 = blockIdx.x & 63;
        const int ks = (blockIdx.x >> 6) * 8 + (tid >> 5);
        const int k0 = ks * 16 + 2 * t4;
        const int n0 = nb16 * 16 + g;
        const float* p00 = Wd + (size_t)k0 * N_SZ + n0;
        uint4 v;
        v.x = h2pack(p00[0],              p00[N_SZ]);
        v.y = h2pack(p00[8 * N_SZ],       p00[9 * N_SZ]);
        v.z = h2pack(p00[8],              p00[N_SZ + 8]);
        v.w = h2pack(p00[8 * N_SZ + 8],   p00[9 * N_SZ + 8]);
        g_Bpack[((size_t)nb16 * NKS + ks) * 32 + lane] = v;
        return;
    }

    // ---- A pack: block = 128 M rows ----
    {
        const float be0 = be[0], be1 = be[1], be2 = be[2], be3 = be[3];
        for (int i = tid; i < NCLS; i += 256) {
            const float4 e = *(const float4*)(We + i * 4);
            sH[i * 2]     = h2pack(e.x + be0, e.y + be1);
            sH[i * 2 + 1] = h2pack(e.z + be2, e.w + be3);
        }
    }
    const int w = tid >> 5;
    const int h = t4 & 1, pq = t4 >> 1;
    const int rowbase = (blockIdx.x - 512) * 128;

    for (int mb = 0; mb < 8; ++mb) {
        __syncthreads();
        {
            const int* src = x + (size_t)(rowbase + mb * 16) * P_SZ;
#pragma unroll
            for (int i = 0; i < 4; ++i) {
                const int cc = i * 256 + tid;
                const int row = cc >> 6, col4 = cc & 63;
                const int4 v = *(const int4*)(src + row * P_SZ + col4 * 4);
                *(int4*)(sX + row * XS + col4 * 4) = v;
            }
        }
        __syncthreads();
        const size_t mbG = (size_t)(rowbase >> 4) + mb;
#pragma unroll
        for (int kk = 0; kk < 8; ++kk) {
            const int ks = kk * 8 + w;
            const int p0 = ks * 4 + pq;
            const int x00 = sX[g * XS + p0];
            const int x10 = sX[(g + 8) * XS + p0];
            const int x01 = sX[g * XS + p0 + 2];
            const int x11 = sX[(g + 8) * XS + p0 + 2];
            uint4 v;
            v.x = sH[x00 * 2 + h];
            v.y = sH[x10 * 2 + h];
            v.z = sH[x01 * 2 + h];
            v.w = sH[x11 * 2 + h];
            g_Apack[(mbG * NKS + ks) * 32 + lane] = v;
        }
    }
}

// ---------------------------------------------------------------------------
// MMA: one k16-step = 16 HMMAs (2 m-tiles x 8 n-tiles).
// ---------------------------------------------------------------------------
__device__ __forceinline__ void mma_kstep(const uint4 a[2], const uint4 b[4],
                                          float c[2][8][4]) {
#pragma unroll
    for (int i4 = 0; i4 < 4; ++i4) {
#pragma unroll
        for (int i = 0; i < 2; ++i) {
            asm volatile(
                "mma.sync.aligned.m16n8k16.row.col.f32.f16.f16.f32 "
                "{%0,%1,%2,%3}, {%4,%5,%6,%7}, {%8,%9}, {%0,%1,%2,%3};"
                : "+f"(c[i][i4 * 2][0]), "+f"(c[i][i4 * 2][1]),
                  "+f"(c[i][i4 * 2][2]), "+f"(c[i][i4 * 2][3])
                : "r"(a[i].x), "r"(a[i].y), "r"(a[i].z), "r"(a[i].w),
                  "r"(b[i4].x), "r"(b[i4].y));
            asm volatile(
                "mma.sync.aligned.m16n8k16.row.col.f32.f16.f16.f32 "
                "{%0,%1,%2,%3}, {%4,%5,%6,%7}, {%8,%9}, {%0,%1,%2,%3};"
                : "+f"(c[i][i4 * 2 + 1][0]), "+f"(c[i][i4 * 2 + 1][1]),
                  "+f"(c[i][i4 * 2 + 1][2]), "+f"(c[i][i4 * 2 + 1][3])
                : "r"(a[i].x), "r"(a[i].y), "r"(a[i].z), "r"(a[i].w),
                  "r"(b[i4].z), "r"(b[i4].w));
        }
    }
}

// ---------------------------------------------------------------------------
// Main GEMM, persistent.  band = bid & 7 is FIXED (B stays warm); m-tiles
// claimed from the band's atomic counter.  SMEM: 3 stages of [A | B] frags.
// ---------------------------------------------------------------------------
__global__ void __launch_bounds__(THREADS, 2)
enc_gemm_kernel(const float* __restrict__ bd, float* __restrict__ out) {
    extern __shared__ uint4 smem[];
    __shared__ int sT;
    const uint32_t sbase = smem_u32(smem);

    const int tid = threadIdx.x;
    const int wid = tid >> 5, lane = tid & 31;
    const int g = lane >> 2, t4 = lane & 3;
    const int warp_m = wid & 3;      // 4 x 32 = 128 M
    const int warp_n = wid >> 2;     // 2 x 64 = 128 N
    const int band = blockIdx.x & 7;
    const int n0 = band * NT;        // fixed n-band per CTA

    const uint4* bsrc = g_Bpack + (size_t)(n0 >> 4) * NKS * 32;

    auto stageA  = [&](int s) -> const uint4* { return smem + (size_t)s * STAGE_U4; };
    auto stageB  = [&](int s) -> const uint4* { return smem + (size_t)s * STAGE_U4 + A_U4; };
    auto stageAaddr = [&](int s) -> uint32_t { return sbase + (uint32_t)s * (STAGE_U4 * 16u); };
    auto stageBaddr = [&](int s) -> uint32_t { return sbase + (uint32_t)s * (STAGE_U4 * 16u) + A_U4 * 16u; };

    float c[2][8][4];
    int m0p = -1;

    for (;;) {
        if (tid == 0) sT = atomicAdd(&g_mctr[band], 1);
        __syncthreads();                 // publishes sT; also protects stage reuse
        const int mi = sT;
        const bool have = (mi < M_TILES);
        const int m0 = mi * MT;
        const uint4* asrc = g_Apack + (size_t)(m0 >> 4) * NKS * 32;

        // per-chunk copy: A 1024 u4 + B 1024 u4 over 256 threads = 4+4 cp16 each
        auto copyAB = [&](int ch, int s) {
            const uint32_t aA = stageAaddr(s), bA = stageBaddr(s);
#pragma unroll
            for (int i = 0; i < 4; ++i) {
                const int cc = i * 256 + tid;
                const int mb = cc >> 7, rem = cc & 127;     // rem = ksl*32+lane
                cp16(aA + (uint32_t)cc * 16u,
                     asrc + ((size_t)mb * NKS + ch * KSC) * 32 + rem);
            }
#pragma unroll
            for (int i = 0; i < 4; ++i) {
                const int cc = i * 256 + tid;
                const int nb = cc >> 7, rem = cc & 127;
                cp16(bA + (uint32_t)cc * 16u,
                     bsrc + ((size_t)nb * NKS + ch * KSC) * 32 + rem);
            }
        };

        if (have) {
            copyAB(0, 0); CP_COMMIT();
            copyAB(1, 1); CP_COMMIT();
        }

        // previous tile's epilogue overlaps the prefetch above
        if (m0p >= 0) {
#pragma unroll
            for (int i = 0; i < 2; ++i) {
                const size_t r0 = (size_t)(m0p + warp_m * 32 + i * 16 + g);
#pragma unroll
                for (int j = 0; j < 8; ++j) {
                    const int col = n0 + warp_n * 64 + j * 8 + t4 * 2;
                    const float2 bb = *(const float2*)(bd + col);
                    float2 v0, v1;
                    v0.x = c[i][j][0] + bb.x;  v0.y = c[i][j][1] + bb.y;
                    v1.x = c[i][j][2] + bb.x;  v1.y = c[i][j][3] + bb.y;
                    *(float2*)(out + r0 * N_SZ + col)       = v0;
                    *(float2*)(out + (r0 + 8) * N_SZ + col) = v1;
                }
            }
        }
        if (!have) break;

#pragma unroll
        for (int i = 0; i < 2; ++i)
#pragma unroll
            for (int j = 0; j < 8; ++j)
#pragma unroll
                for (int q = 0; q < 4; ++q) c[i][j][q] = 0.0f;

        // ---- mainloop (identical schedule to R11) ----
        for (int ch = 0; ch < NCHUNK; ++ch) {
            const int st = ch % 3;

            CP_WAIT1();              // stage st landed
            __syncthreads();         // stage (ch+2)%3 free

            if (ch + 2 < NCHUNK) copyAB(ch + 2, (ch + 2) % 3);
            CP_COMMIT();

            const uint4* aPtr = stageA(st) + (warp_m * 2) * (KSC * 32) + lane;
            const uint4* bPtr = stageB(st) + (warp_n * 4) * (KSC * 32) + lane;

#pragma unroll
            for (int ksl = 0; ksl < KSC; ++ksl) {
                uint4 a[2], b[4];
                a[0] = aPtr[ksl * 32];
                a[1] = aPtr[KSC * 32 + ksl * 32];
#pragma unroll
                for (int i = 0; i < 4; ++i)
                    b[i] = bPtr[i * (KSC * 32) + ksl * 32];
                mma_kstep(a, b, c);
            }
        }

        m0p = m0;
    }
}

// ---------------------------------------------------------------------------
// kernel_launch
// ---------------------------------------------------------------------------
extern "C" void kernel_launch(void* const* d_in, const int* in_sizes, int n_in,
                              void* d_out, int out_size) {
    const int*   x  = (const int*)d_in[0];
    const float* We = (const float*)d_in[1];
    const float* be = (const float*)d_in[2];
    const float* Wd = (const float*)d_in[3];
    const float* bd = (const float*)d_in[4];
    float* out = (float*)d_out;

    cudaStreamCaptureStatus cs = cudaStreamCaptureStatusNone;
    cudaError_t qerr = cudaStreamIsCapturing((cudaStream_t)0, &cs);
    const bool capturing = (qerr != cudaSuccess) || (cs != cudaStreamCaptureStatusNone);
    if (!capturing) {
        cudaFuncSetAttribute(enc_gemm_kernel,
                             cudaFuncAttributeMaxDynamicSharedMemorySize, SMEM_BYTES);
    }
    (void)cudaGetLastError();

    pack_all_kernel<<<640, 256>>>(Wd, x, We, be);
    enc_gemm_kernel<<<GRID_P, THREADS, SMEM_BYTES>>>(bd, out);
}

// round 17
// speedup vs baseline: 1.3115x; 1.3115x over previous
#include <cuda_runtime.h>
#include <cuda_fp16.h>
#include <cstdint>
#include <cstring>

// ============================================================================
// FlattenedObsEncoder: out[16384,1024] = (gather(W_embed,x)+b_embed) @ W_dense + b_dense
// fp16 m16n8k16 mma.sync GEMM, fp32 accumulation.
// R17 = R11 GEMM verbatim (best known: plain 1024-CTA launch, 3-stage pipeline,
// compiler-scheduled inner loop) + ONE merged prepass launch (512 B-pack blocks
// + 256 A-pack blocks).
// CTA 128x128, 256 threads, warp tile 32x64, 2 CTAs/SM.
// ============================================================================

#define B_SZ   16384
#define P_SZ   256
#define K_SZ   1024
#define N_SZ   1024
#define NCLS   1024
#define MT     128
#define NT     128
#define NKS    (K_SZ / 16)    // 64 global k16-steps
#define KSC    4              // ksteps per chunk
#define NCHUNK (NKS / KSC)    // 16
#define THREADS 256
#define A_U4   1024
#define B_U4   1024
#define STAGE_U4 (A_U4 + B_U4)               // 2048 uint4 = 32 KB
#define NSTAGE 3
#define SMEM_BYTES (STAGE_U4 * NSTAGE * 16)  // 98,304 B -> 2 CTAs/SM

// B fragments: uint4 index = (nb16*NKS + ks)*32 + lane
//   lane (g = lane>>2, t4 = lane&3):
//   .x={B[k0][n0+g],B[k0+1][n0+g]} .y={B[k0+8][..],B[k0+9][..]}  (n-tile jj=0)
//   .z,.w same with n0+8                                        (n-tile jj=1)
//   k0 = ks*16 + 2*t4, n0 = nb16*16
__device__ uint4 g_Bpack[(size_t)(N_SZ / 16) * NKS * 32];

// A fragments: uint4 index = (mb*NKS + ks)*32 + lane
//   .x={A[r][k0],A[r][k0+1]} .y={A[r+8][k0],A[r+8][k0+1]}
//   .z={A[r][k0+8],A[r][k0+9]} .w={A[r+8][k0+8],A[r+8][k0+9]}
//   r = mb*16 + g, k0 = ks*16 + 2*t4
__device__ uint4 g_Apack[(size_t)(B_SZ / 16) * NKS * 32];

// ---------------------------------------------------------------------------
__device__ __forceinline__ uint32_t smem_u32(const void* p) {
    uint32_t a;
    asm("{ .reg .u64 t; cvta.to.shared.u64 t, %1; cvt.u32.u64 %0, t; }" : "=r"(a) : "l"(p));
    return a;
}
__device__ __forceinline__ void cp16(uint32_t s, const void* g) {
    asm volatile("cp.async.cg.shared.global [%0], [%1], 16;" :: "r"(s), "l"(g));
}
#define CP_COMMIT() asm volatile("cp.async.commit_group;" ::: "memory")
#define CP_WAIT1()  asm volatile("cp.async.wait_group 1;" ::: "memory")

__device__ __forceinline__ uint32_t h2pack(float lo, float hi) {
    const __half2 h = __floats2half2_rn(lo, hi);   // low half = lo
    uint32_t u;
    memcpy(&u, &h, 4);
    return u;
}

// ---------------------------------------------------------------------------
// Merged prepass (ONE launch).
//   Blocks [0,512):   W_dense -> fp16 B-fragment pack (8 ks x 16 n each).
//   Blocks [512,768): gather+bias -> fp16 A-fragment pack (64 M rows each).
// ---------------------------------------------------------------------------
#define XS 260   // padded x-row stride in ints (260 % 32 = 4 -> g spreads banks)

__global__ void __launch_bounds__(256)
pack_all_kernel(const float* __restrict__ Wd,
                const int* __restrict__ x, const float* __restrict__ We,
                const float* __restrict__ be) {
    __shared__ uint32_t sH[NCLS * 2];
    __shared__ int sX[16 * XS];

    const int tid = threadIdx.x;
    const int lane = tid & 31;
    const int g = lane >> 2, t4 = lane & 3;

    if (blockIdx.x < 512) {
        // ---- B pack: block = (nb16, ks-group of 8) ----
        const int nb16 = blockIdx.x & 63;
        const int ks = (blockIdx.x >> 6) * 8 + (tid >> 5);
        const int k0 = ks * 16 + 2 * t4;
        const int n0 = nb16 * 16 + g;
        const float* p00 = Wd + (size_t)k0 * N_SZ + n0;
        uint4 v;
        v.x = h2pack(p00[0],              p00[N_SZ]);
        v.y = h2pack(p00[8 * N_SZ],       p00[9 * N_SZ]);
        v.z = h2pack(p00[8],              p00[N_SZ + 8]);
        v.w = h2pack(p00[8 * N_SZ + 8],   p00[9 * N_SZ + 8]);
        g_Bpack[((size_t)nb16 * NKS + ks) * 32 + lane] = v;
        return;
    }

    // ---- A pack: block = 64 M rows ----
    {
        const float be0 = be[0], be1 = be[1], be2 = be[2], be3 = be[3];
        for (int i = tid; i < NCLS; i += 256) {
            const float4 e = *(const float4*)(We + i * 4);
            sH[i * 2]     = h2pack(e.x + be0, e.y + be1);
            sH[i * 2 + 1] = h2pack(e.z + be2, e.w + be3);
        }
    }
    const int w = tid >> 5;
    const int h = t4 & 1, pq = t4 >> 1;
    const int rowbase = (blockIdx.x - 512) * 64;

    for (int mb = 0; mb < 4; ++mb) {
        __syncthreads();
        {
            const int* src = x + (size_t)(rowbase + mb * 16) * P_SZ;
#pragma unroll
            for (int i = 0; i < 4; ++i) {
                const int cc = i * 256 + tid;
                const int row = cc >> 6, col4 = cc & 63;
                const int4 v = *(const int4*)(src + row * P_SZ + col4 * 4);
                *(int4*)(sX + row * XS + col4 * 4) = v;
            }
        }
        __syncthreads();
        const size_t mbG = (size_t)(rowbase >> 4) + mb;
#pragma unroll
        for (int kk = 0; kk < 8; ++kk) {
            const int ks = kk * 8 + w;
            const int p0 = ks * 4 + pq;
            const int x00 = sX[g * XS + p0];
            const int x10 = sX[(g + 8) * XS + p0];
            const int x01 = sX[g * XS + p0 + 2];
            const int x11 = sX[(g + 8) * XS + p0 + 2];
            uint4 v;
            v.x = sH[x00 * 2 + h];
            v.y = sH[x10 * 2 + h];
            v.z = sH[x01 * 2 + h];
            v.w = sH[x11 * 2 + h];
            g_Apack[(mbG * NKS + ks) * 32 + lane] = v;
        }
    }
}

// ---------------------------------------------------------------------------
// MMA: one k16-step = 16 HMMAs (2 m-tiles x 8 n-tiles).
// ---------------------------------------------------------------------------
__device__ __forceinline__ void mma_kstep(const uint4 a[2], const uint4 b[4],
                                          float c[2][8][4]) {
#pragma unroll
    for (int i4 = 0; i4 < 4; ++i4) {
#pragma unroll
        for (int i = 0; i < 2; ++i) {
            asm volatile(
                "mma.sync.aligned.m16n8k16.row.col.f32.f16.f16.f32 "
                "{%0,%1,%2,%3}, {%4,%5,%6,%7}, {%8,%9}, {%0,%1,%2,%3};"
                : "+f"(c[i][i4 * 2][0]), "+f"(c[i][i4 * 2][1]),
                  "+f"(c[i][i4 * 2][2]), "+f"(c[i][i4 * 2][3])
                : "r"(a[i].x), "r"(a[i].y), "r"(a[i].z), "r"(a[i].w),
                  "r"(b[i4].x), "r"(b[i4].y));
            asm volatile(
                "mma.sync.aligned.m16n8k16.row.col.f32.f16.f16.f32 "
                "{%0,%1,%2,%3}, {%4,%5,%6,%7}, {%8,%9}, {%0,%1,%2,%3};"
                : "+f"(c[i][i4 * 2 + 1][0]), "+f"(c[i][i4 * 2 + 1][1]),
                  "+f"(c[i][i4 * 2 + 1][2]), "+f"(c[i][i4 * 2 + 1][3])
                : "r"(a[i].x), "r"(a[i].y), "r"(a[i].z), "r"(a[i].w),
                  "r"(b[i4].z), "r"(b[i4].w));
        }
    }
}

// ---------------------------------------------------------------------------
// Main GEMM (R11 verbatim).  SMEM: 3 stages of [A 1024 u4 | B 1024 u4].
// Stage layout: A [mb][ksl][lane], B [nb16][ksl][lane].
// ---------------------------------------------------------------------------
__global__ void __launch_bounds__(THREADS, 2)
enc_gemm_kernel(const float* __restrict__ bd, float* __restrict__ out) {
    extern __shared__ uint4 smem[];
    const uint32_t sbase = smem_u32(smem);

    const int tid = threadIdx.x;
    const int wid = tid >> 5, lane = tid & 31;
    const int g = lane >> 2, t4 = lane & 3;
    const int warp_m = wid & 3;      // 4 x 32 = 128 M
    const int warp_n = wid >> 2;     // 2 x 64 = 128 N
    const int n0 = blockIdx.x * NT;
    const int m0 = blockIdx.y * MT;

    const uint4* asrc = g_Apack + (size_t)(m0 >> 4) * NKS * 32;
    const uint4* bsrc = g_Bpack + (size_t)(n0 >> 4) * NKS * 32;

    float c[2][8][4];
#pragma unroll
    for (int i = 0; i < 2; ++i)
#pragma unroll
        for (int j = 0; j < 8; ++j)
#pragma unroll
            for (int q = 0; q < 4; ++q) c[i][j][q] = 0.0f;

    auto stageA  = [&](int s) -> const uint4* { return smem + (size_t)s * STAGE_U4; };
    auto stageB  = [&](int s) -> const uint4* { return smem + (size_t)s * STAGE_U4 + A_U4; };
    auto stageAaddr = [&](int s) -> uint32_t { return sbase + (uint32_t)s * (STAGE_U4 * 16u); };
    auto stageBaddr = [&](int s) -> uint32_t { return sbase + (uint32_t)s * (STAGE_U4 * 16u) + A_U4 * 16u; };

    // per-chunk copy: A 1024 u4 + B 1024 u4 over 256 threads = 4+4 cp16 each
    auto copyAB = [&](int ch, int s) {
        const uint32_t aA = stageAaddr(s), bA = stageBaddr(s);
#pragma unroll
        for (int i = 0; i < 4; ++i) {
            const int cc = i * 256 + tid;
            const int mb = cc >> 7, rem = cc & 127;     // rem = ksl*32+lane
            cp16(aA + (uint32_t)cc * 16u,
                 asrc + ((size_t)mb * NKS + ch * KSC) * 32 + rem);
        }
#pragma unroll
        for (int i = 0; i < 4; ++i) {
            const int cc = i * 256 + tid;
            const int nb = cc >> 7, rem = cc & 127;
            cp16(bA + (uint32_t)cc * 16u,
                 bsrc + ((size_t)nb * NKS + ch * KSC) * 32 + rem);
        }
    };

    // ---- prologue ----
    copyAB(0, 0); CP_COMMIT();
    copyAB(1, 1); CP_COMMIT();

    // ---- mainloop ----
    for (int ch = 0; ch < NCHUNK; ++ch) {
        const int st = ch % 3;

        CP_WAIT1();              // stage st landed
        __syncthreads();         // stage (ch+2)%3 free

        if (ch + 2 < NCHUNK) copyAB(ch + 2, (ch + 2) % 3);
        CP_COMMIT();

        const uint4* aPtr = stageA(st) + (warp_m * 2) * (KSC * 32) + lane;
        const uint4* bPtr = stageB(st) + (warp_n * 4) * (KSC * 32) + lane;

#pragma unroll
        for (int ksl = 0; ksl < KSC; ++ksl) {
            uint4 a[2], b[4];
            a[0] = aPtr[ksl * 32];
            a[1] = aPtr[KSC * 32 + ksl * 32];
#pragma unroll
            for (int i = 0; i < 4; ++i)
                b[i] = bPtr[i * (KSC * 32) + ksl * 32];
            mma_kstep(a, b, c);
        }
    }

    // ---- epilogue: accum + b_dense -> out ----
#pragma unroll
    for (int i = 0; i < 2; ++i) {
        const size_t r0 = (size_t)(m0 + warp_m * 32 + i * 16 + g);
#pragma unroll
        for (int j = 0; j < 8; ++j) {
            const int col = n0 + warp_n * 64 + j * 8 + t4 * 2;
            const float2 bb = *(const float2*)(bd + col);
            float2 v0, v1;
            v0.x = c[i][j][0] + bb.x;  v0.y = c[i][j][1] + bb.y;
            v1.x = c[i][j][2] + bb.x;  v1.y = c[i][j][3] + bb.y;
            *(float2*)(out + r0 * N_SZ + col)       = v0;
            *(float2*)(out + (r0 + 8) * N_SZ + col) = v1;
        }
    }
}

// ---------------------------------------------------------------------------
// kernel_launch
// ---------------------------------------------------------------------------
extern "C" void kernel_launch(void* const* d_in, const int* in_sizes, int n_in,
                              void* d_out, int out_size) {
    const int*   x  = (const int*)d_in[0];
    const float* We = (const float*)d_in[1];
    const float* be = (const float*)d_in[2];
    const float* Wd = (const float*)d_in[3];
    const float* bd = (const float*)d_in[4];
    float* out = (float*)d_out;

    cudaStreamCaptureStatus cs = cudaStreamCaptureStatusNone;
    cudaError_t qerr = cudaStreamIsCapturing((cudaStream_t)0, &cs);
    const bool capturing = (qerr != cudaSuccess) || (cs != cudaStreamCaptureStatusNone);
    if (!capturing) {
        cudaFuncSetAttribute(enc_gemm_kernel,
                             cudaFuncAttributeMaxDynamicSharedMemorySize, SMEM_BYTES);
    }
    (void)cudaGetLastError();

    pack_all_kernel<<<768, 256>>>(Wd, x, We, be);
    enc_gemm_kernel<<<dim3(N_SZ / NT, B_SZ / MT), THREADS, SMEM_BYTES>>>(bd, out);
}